// round 10
// baseline (speedup 1.0000x reference)
#include <cuda_runtime.h>
#include <cuda_fp16.h>
#include <cstdint>

#define BN 8
#define IC 512
#define OC 512
#define HH 32
#define WW 32
#define NTL 2048    // total 2x2 output tiles = BN * 16 * 16

#define RC_DENSE 0.04419417382415922f     // 1/sqrt(512)
#define RC_CONV  0.014731391274719739f    // 1/sqrt(9*512)

// ---------------- device scratch (no runtime allocation) ----------------
__device__ float g_style[BN * IC];
__device__ float g_scale[BN * OC];
__device__ float g_ss[IC * OC];
__device__ __align__(128) __half g_U[16 * OC * IC];   // [j][oc][ic]
__device__ __align__(128) __half g_V[16 * NTL * IC];  // [j][tile][ic]
__device__ __align__(128) float  g_m[(size_t)16 * OC * NTL]; // [j][oc][tile]

// ---------------- prologue: style / demod ----------------
__global__ void style_kernel(const float* __restrict__ w,
                             const float* __restrict__ dense_w,
                             const float* __restrict__ dense_b) {
    __shared__ float wrow[IC];
    int b = blockIdx.x;
    for (int j = threadIdx.x; j < IC; j += blockDim.x) wrow[j] = w[b * IC + j];
    __syncthreads();
    for (int i = threadIdx.x; i < IC; i += blockDim.x) {
        float acc = 0.f;
        #pragma unroll 8
        for (int j = 0; j < IC; j++) acc = fmaf(wrow[j], dense_w[j * IC + i], acc);
        g_style[b * IC + i] = RC_DENSE * acc + dense_b[i] + 1.0f;
    }
}

__global__ void ss_kernel(const float* __restrict__ conv_w) {
    int idx = blockIdx.x * blockDim.x + threadIdx.x;
    if (idx >= IC * OC) return;
    float s = 0.f;
    #pragma unroll
    for (int k = 0; k < 9; k++) {
        float v = conv_w[k * IC * OC + idx];
        s = fmaf(v, v, s);
    }
    g_ss[idx] = s;
}

__global__ void demod_kernel() {
    __shared__ float s2[IC];
    int b = blockIdx.x;
    for (int i = threadIdx.x; i < IC; i += blockDim.x) {
        float s = g_style[b * IC + i];
        s2[i] = s * s;
    }
    __syncthreads();
    for (int oc = threadIdx.x; oc < OC; oc += blockDim.x) {
        float acc = 0.f;
        #pragma unroll 8
        for (int i = 0; i < IC; i++) acc = fmaf(s2[i], g_ss[i * OC + oc], acc);
        g_scale[b * OC + oc] = RC_CONV * rsqrtf(RC_CONV * RC_CONV * acc + 1e-8f);
    }
}

// ---------------- weight transform: U = G g G^T  -> [j][oc][ic] fp16 ----------------
__global__ __launch_bounds__(1024)
void uw_kernel(const float* __restrict__ conv_w) {
    __shared__ float f[9][32][33];
    int ic0 = blockIdx.x * 32, oc0 = blockIdx.y * 32;
    int t = threadIdx.x;
    for (int e = t; e < 9 * 1024; e += 1024) {
        int k = e >> 10, r = (e >> 5) & 31, c = e & 31;
        f[k][r][c] = conv_w[(size_t)k * IC * OC + (size_t)(ic0 + r) * OC + oc0 + c];
    }
    __syncthreads();
    int ol = t >> 5, il = t & 31;   // warp lanes = il -> coalesced U writes
    float g[9];
    #pragma unroll
    for (int k = 0; k < 9; k++) g[k] = f[k][il][ol];
    float tr[4][3];
    #pragma unroll
    for (int c = 0; c < 3; c++) {
        tr[0][c] = g[c];
        tr[1][c] = 0.5f * (g[c] + g[3 + c] + g[6 + c]);
        tr[2][c] = 0.5f * (g[c] - g[3 + c] + g[6 + c]);
        tr[3][c] = g[6 + c];
    }
    size_t base = (size_t)(oc0 + ol) * IC + ic0 + il;
    #pragma unroll
    for (int i = 0; i < 4; i++) {
        float u0 = tr[i][0];
        float u1 = 0.5f * (tr[i][0] + tr[i][1] + tr[i][2]);
        float u2 = 0.5f * (tr[i][0] - tr[i][1] + tr[i][2]);
        float u3 = tr[i][2];
        g_U[(size_t)(i * 4 + 0) * OC * IC + base] = __float2half_rn(u0);
        g_U[(size_t)(i * 4 + 1) * OC * IC + base] = __float2half_rn(u1);
        g_U[(size_t)(i * 4 + 2) * OC * IC + base] = __float2half_rn(u2);
        g_U[(size_t)(i * 4 + 3) * OC * IC + base] = __float2half_rn(u3);
    }
}

// ---------------- data transform: V = B^T (style*x) B -> [j][tile][ic] fp16 ----------
__global__ __launch_bounds__(256)
void vx_kernel(const float* __restrict__ x) {
    __shared__ float xs[16][4][33];
    __shared__ unsigned short sv[16 * 16 * 18];   // [(j*16+tj)*18 + icl]
    int blk = blockIdx.x;            // b*16 + ti
    int b = blk >> 4, ti = blk & 15;
    int t = threadIdx.x;
    int icl_t = t >> 4, tj_t = t & 15;
    int tbase = blk << 4;

    for (int cc = 0; cc < 32; cc++) {
        int ic0 = cc * 16;
        __syncthreads();
        // stage 1: load rows 2ti-1..2ti+2 x 32 w x 16 ic, modulated
        #pragma unroll
        for (int i = 0; i < 8; i++) {
            int e = t + i * 256;
            int icl = e >> 7, row = (e >> 5) & 3, w = e & 31;
            int h = 2 * ti - 1 + row;
            float v = 0.f;
            if ((unsigned)h < HH)
                v = x[(((size_t)b * IC + ic0 + icl) * HH + h) * WW + w] * g_style[b * IC + ic0 + icl];
            xs[icl][row][w] = v;
        }
        __syncthreads();
        // stage 2: per (ic, tj) 4x4 transform
        {
            float d[4][4];
            #pragma unroll
            for (int r = 0; r < 4; r++)
                #pragma unroll
                for (int c = 0; c < 4; c++) {
                    int w = 2 * tj_t - 1 + c;
                    d[r][c] = ((unsigned)w < WW) ? xs[icl_t][r][w] : 0.f;
                }
            float tr[4][4];
            #pragma unroll
            for (int c = 0; c < 4; c++) {
                tr[0][c] = d[0][c] - d[2][c];
                tr[1][c] = d[1][c] + d[2][c];
                tr[2][c] = d[2][c] - d[1][c];
                tr[3][c] = d[1][c] - d[3][c];
            }
            #pragma unroll
            for (int i = 0; i < 4; i++) {
                float v0 = tr[i][0] - tr[i][2];
                float v1 = tr[i][1] + tr[i][2];
                float v2 = tr[i][2] - tr[i][1];
                float v3 = tr[i][1] - tr[i][3];
                sv[((i * 4 + 0) * 16 + tj_t) * 18 + icl_t] = __half_as_ushort(__float2half_rn(v0));
                sv[((i * 4 + 1) * 16 + tj_t) * 18 + icl_t] = __half_as_ushort(__float2half_rn(v1));
                sv[((i * 4 + 2) * 16 + tj_t) * 18 + icl_t] = __half_as_ushort(__float2half_rn(v2));
                sv[((i * 4 + 3) * 16 + tj_t) * 18 + icl_t] = __half_as_ushort(__float2half_rn(v3));
            }
        }
        __syncthreads();
        // stage 3: coalesced 32B writes, thread -> (j, tj)
        {
            int j = t >> 4, tj = t & 15;
            const unsigned int* s32 = (const unsigned int*)&sv[(j * 16 + tj) * 18];
            uint4 p0 = make_uint4(s32[0], s32[1], s32[2], s32[3]);
            uint4 p1 = make_uint4(s32[4], s32[5], s32[6], s32[7]);
            uint4* dst = (uint4*)(g_V + ((size_t)j * NTL + tbase + tj) * IC + ic0);
            dst[0] = p0; dst[1] = p1;
        }
    }
}

// ---------------- Winograd GEMM: m[j][oc][tile] = U[j] x V[j]^T ----------------
#define PAD 40
#define SA_O(buf) ((buf) * 5120)
#define SB_O(buf) (15360 + (buf) * 5120)
#define GEMM_SM_BYTES (30720 * 2)

__device__ __forceinline__ void mma_f16(float* c,
                                        const uint32_t* a, uint32_t b0, uint32_t b1) {
    asm volatile(
        "mma.sync.aligned.m16n8k16.row.col.f32.f16.f16.f32 "
        "{%0,%1,%2,%3}, {%4,%5,%6,%7}, {%8,%9}, {%0,%1,%2,%3};"
        : "+f"(c[0]), "+f"(c[1]), "+f"(c[2]), "+f"(c[3])
        : "r"(a[0]), "r"(a[1]), "r"(a[2]), "r"(a[3]), "r"(b0), "r"(b1));
}
__device__ __forceinline__ void ldsm4(uint32_t* r, uint32_t a) {
    asm volatile("ldmatrix.sync.aligned.m8n8.x4.shared.b16 {%0,%1,%2,%3}, [%4];"
                 : "=r"(r[0]), "=r"(r[1]), "=r"(r[2]), "=r"(r[3]) : "r"(a));
}
__device__ __forceinline__ void cp16(uint32_t dst, const void* src) {
    asm volatile("cp.async.ca.shared.global [%0], [%1], 16;"
                 :: "r"(dst), "l"(src) : "memory");
}
#define CP_COMMIT() asm volatile("cp.async.commit_group;" ::: "memory")
#define CP_WAIT0()  asm volatile("cp.async.wait_group 0;" ::: "memory")
#define CP_WAIT1()  asm volatile("cp.async.wait_group 1;" ::: "memory")
__device__ __forceinline__ uint32_t smem_u32(const void* p) {
    uint32_t a;
    asm("{ .reg .u64 t; cvta.to.shared.u64 t, %1; cvt.u32.u64 %0, t; }" : "=r"(a) : "l"(p));
    return a;
}

__global__ __launch_bounds__(256, 2)
void wino_gemm_kernel() {
    extern __shared__ unsigned short sm[];
    const uint32_t smb = smem_u32(sm);
    const int tid = threadIdx.x;
    const int wid = tid >> 5, lane = tid & 31;
    const int gr = lane >> 2, tig = lane & 3;
    const int wm = wid & 3, wn = wid >> 2;

    const int nt0 = blockIdx.x * 128;   // tile dim (N)
    const int oc0 = blockIdx.y * 128;   // oc  dim (M)
    const int j = blockIdx.z;

    const __half* Abase = g_U + (size_t)j * OC * IC + (size_t)oc0 * IC;
    const __half* Bbase = g_V + (size_t)j * NTL * IC + (size_t)nt0 * IC;

    const int r16 = ((lane >> 3) & 1) * 8 + (lane & 7);
    const int kq8 = (lane >> 4) * 8;
    const int aoff = (wm * 32 + r16) * PAD + kq8;
    const int rb = (lane & 7) + ((lane >> 4) & 1) * 8;
    const int kb8 = ((lane >> 3) & 1) * 8;
    const int boff = (wn * 64 + rb) * PAD + kb8;

    const int rL = tid >> 1, hL = tid & 1;
    const __half* aRow = Abase + (size_t)rL * IC + hL * 16;
    const __half* bRow = Bbase + (size_t)rL * IC + hL * 16;
    const uint32_t ldst = (uint32_t)(rL * PAD + hL * 16) * 2;

    float acc[2][8][4];
    #pragma unroll
    for (int mt = 0; mt < 2; mt++)
        #pragma unroll
        for (int nt = 0; nt < 8; nt++)
            #pragma unroll
            for (int q = 0; q < 4; q++) acc[mt][nt][q] = 0.f;

    // preload K-chunks 0,1
    #pragma unroll
    for (int pc = 0; pc < 2; pc++) {
        cp16(smb + SA_O(pc) * 2 + ldst,      aRow + pc * 32);
        cp16(smb + SA_O(pc) * 2 + ldst + 16, aRow + pc * 32 + 8);
        cp16(smb + SB_O(pc) * 2 + ldst,      bRow + pc * 32);
        cp16(smb + SB_O(pc) * 2 + ldst + 16, bRow + pc * 32 + 8);
        CP_COMMIT();
    }

    for (int c = 0; c < 16; c++) {
        if (c < 14) { CP_WAIT1(); } else { CP_WAIT0(); }
        __syncthreads();
        if (c < 14) {
            int buf = (c + 2) % 3;
            cp16(smb + SA_O(buf) * 2 + ldst,      aRow + (c + 2) * 32);
            cp16(smb + SA_O(buf) * 2 + ldst + 16, aRow + (c + 2) * 32 + 8);
            cp16(smb + SB_O(buf) * 2 + ldst,      bRow + (c + 2) * 32);
            cp16(smb + SB_O(buf) * 2 + ldst + 16, bRow + (c + 2) * 32 + 8);
            CP_COMMIT();
        }
        int buf = c % 3;
        uint32_t abase_s = smb + (uint32_t)(SA_O(buf) + aoff) * 2;
        uint32_t bbase_s = smb + (uint32_t)(SB_O(buf) + boff) * 2;
        #pragma unroll
        for (int ks = 0; ks < 2; ks++) {
            uint32_t ah[2][4];
            ldsm4(ah[0], abase_s + (ks * 16) * 2);
            ldsm4(ah[1], abase_s + (16 * PAD + ks * 16) * 2);
            #pragma unroll
            for (int np = 0; np < 4; np++) {
                uint32_t bh[4];
                ldsm4(bh, bbase_s + (np * 16 * PAD + ks * 16) * 2);
                mma_f16(acc[0][2 * np],     ah[0], bh[0], bh[1]);
                mma_f16(acc[1][2 * np],     ah[1], bh[0], bh[1]);
                mma_f16(acc[0][2 * np + 1], ah[0], bh[2], bh[3]);
                mma_f16(acc[1][2 * np + 1], ah[1], bh[2], bh[3]);
            }
        }
    }

    // epilogue: fp32 m, 8B stores
    float* mbase = g_m + ((size_t)j * OC + oc0) * NTL + nt0;
    #pragma unroll
    for (int mt = 0; mt < 2; mt++) {
        int row = wm * 32 + mt * 16 + gr;
        #pragma unroll
        for (int nt = 0; nt < 8; nt++) {
            int col = wn * 64 + nt * 8 + tig * 2;
            *(float2*)(mbase + (size_t)row * NTL + col) =
                make_float2(acc[mt][nt][0], acc[mt][nt][1]);
            *(float2*)(mbase + (size_t)(row + 8) * NTL + col) =
                make_float2(acc[mt][nt][2], acc[mt][nt][3]);
        }
    }
}

// ---------------- inverse transform: y = A^T M A * scale ----------------
__global__ __launch_bounds__(256)
void inv_kernel(float* __restrict__ y) {
    int t = threadIdx.x;
    int ocl = t >> 4, tj = t & 15;
    int oc = blockIdx.x * 16 + ocl;
    int blk = blockIdx.y;            // b*16 + ti
    int b = blk >> 4, ti = blk & 15;
    int tile = (blk << 4) + tj;

    float M[4][4];
    #pragma unroll
    for (int j = 0; j < 16; j++)
        M[j >> 2][j & 3] = g_m[((size_t)j * OC + oc) * NTL + tile];

    float z[2][4];
    #pragma unroll
    for (int c = 0; c < 4; c++) {
        z[0][c] = M[0][c] + M[1][c] + M[2][c];
        z[1][c] = M[1][c] - M[2][c] - M[3][c];
    }
    float s = g_scale[b * OC + oc];
    #pragma unroll
    for (int r = 0; r < 2; r++) {
        float y0 = (z[r][0] + z[r][1] + z[r][2]) * s;
        float y1 = (z[r][1] - z[r][2] - z[r][3]) * s;
        *(float2*)(y + (((size_t)b * OC + oc) * HH + 2 * ti + r) * WW + 2 * tj) =
            make_float2(y0, y1);
    }
}

// ---------------------------------------------------------------------------
extern "C" void kernel_launch(void* const* d_in, const int* in_sizes, int n_in,
                              void* d_out, int out_size) {
    const float* x       = (const float*)d_in[0];
    const float* w       = (const float*)d_in[1];
    const float* conv_w  = (const float*)d_in[2];
    const float* dense_w = (const float*)d_in[3];
    const float* dense_b = (const float*)d_in[4];
    float* y = (float*)d_out;

    style_kernel<<<BN, 256>>>(w, dense_w, dense_b);
    ss_kernel<<<(IC * OC) / 256, 256>>>(conv_w);
    demod_kernel<<<BN, 512>>>();
    uw_kernel<<<dim3(IC / 32, OC / 32), 1024>>>(conv_w);
    vx_kernel<<<BN * 16, 256>>>(x);

    static bool attr_set = false;
    if (!attr_set) {
        cudaFuncSetAttribute(wino_gemm_kernel,
                             cudaFuncAttributeMaxDynamicSharedMemorySize, GEMM_SM_BYTES);
        attr_set = true;
    }
    wino_gemm_kernel<<<dim3(NTL / 128, OC / 128, 16), 256, GEMM_SM_BYTES>>>();
    inv_kernel<<<dim3(OC / 16, BN * 16), 256>>>(y);
}

// round 11
// speedup vs baseline: 1.4367x; 1.4367x over previous
#include <cuda_runtime.h>
#include <cuda_fp16.h>
#include <cstdint>

#define BN 8
#define IC 512
#define OC 512
#define HH 32
#define WW 32

#define RC_DENSE 0.04419417382415922f     // 1/sqrt(512)
#define RC_CONV  0.014731391274719739f    // 1/sqrt(9*512)

// ---------------- device scratch (no runtime allocation) ----------------
__device__ float g_style[BN * IC];
__device__ float g_scale[BN * OC];
__device__ float g_ss[IC * OC];
// weights transposed to [tap][oc][ic], fp16
__device__ __align__(128) __half g_wq[9 * OC * IC];
// modulated input in NHWC: [b][h][w][ic], fp16
__device__ __align__(128) __half g_xm[BN * HH * WW * IC];

// ---------------- prologue kernels ----------------
__global__ void style_kernel(const float* __restrict__ w,
                             const float* __restrict__ dense_w,
                             const float* __restrict__ dense_b) {
    __shared__ float wrow[IC];
    int b = blockIdx.x;
    for (int j = threadIdx.x; j < IC; j += blockDim.x) wrow[j] = w[b * IC + j];
    __syncthreads();
    for (int i = threadIdx.x; i < IC; i += blockDim.x) {
        float acc = 0.f;
        #pragma unroll 8
        for (int j = 0; j < IC; j++) acc = fmaf(wrow[j], dense_w[j * IC + i], acc);
        g_style[b * IC + i] = RC_DENSE * acc + dense_b[i] + 1.0f;
    }
}

// conv_w[k][ic][oc] -> wq[k][oc][ic] (fp16) AND ss[ic][oc] = sum_k w^2 (fused)
__global__ void wtrans_kernel(const float* __restrict__ conv_w) {
    __shared__ float tile[32][33];
    int ic0 = blockIdx.x * 32, oc0 = blockIdx.y * 32;
    int t = threadIdx.x, col = t & 31, row0 = t >> 5;
    int r = t >> 3, pp = t & 7;
    float ssacc[4] = {0.f, 0.f, 0.f, 0.f};
    for (int k = 0; k < 9; k++) {
        __syncthreads();
        #pragma unroll
        for (int rr = 0; rr < 4; rr++) {
            int i = rr * 8 + row0;  // ic
            float v = conv_w[((size_t)(k * IC + ic0 + i)) * OC + oc0 + col];
            tile[i][col] = v;
            ssacc[rr] = fmaf(v, v, ssacc[rr]);
        }
        __syncthreads();
        size_t base = ((size_t)(k * OC + oc0 + r)) * IC + ic0;
        #pragma unroll
        for (int it = 0; it < 2; it++) {
            int ci = 2 * (it * 8 + pp);
            *(__half2*)(g_wq + base + ci) =
                __halves2half2(__float2half_rn(tile[ci][r]), __float2half_rn(tile[ci + 1][r]));
        }
    }
    #pragma unroll
    for (int rr = 0; rr < 4; rr++)
        g_ss[(size_t)(ic0 + rr * 8 + row0) * OC + oc0 + col] = ssacc[rr];
}

__global__ void demod_kernel() {
    __shared__ float s2[IC];
    int b = blockIdx.x;
    for (int i = threadIdx.x; i < IC; i += blockDim.x) {
        float s = g_style[b * IC + i];
        s2[i] = s * s;
    }
    __syncthreads();
    for (int oc = threadIdx.x; oc < OC; oc += blockDim.x) {
        float acc = 0.f;
        #pragma unroll 8
        for (int i = 0; i < IC; i++) acc = fmaf(s2[i], g_ss[i * OC + oc], acc);
        g_scale[b * OC + oc] = RC_CONV * rsqrtf(RC_CONV * RC_CONV * acc + 1e-8f);
    }
}

// x[b][ic][h][w] * style[b][ic] -> xm[b][h][w][ic] (fp16)
__global__ void xtrans_kernel(const float* __restrict__ x) {
    __shared__ float tile[32][33];
    int ic0 = blockIdx.x * 32, h = blockIdx.y, b = blockIdx.z;
    int t = threadIdx.x, col = t & 31, row0 = t >> 5;
    #pragma unroll
    for (int rr = 0; rr < 4; rr++) {
        int i = rr * 8 + row0;  // ic
        tile[i][col] = x[(((size_t)b * IC + ic0 + i) * HH + h) * WW + col] * g_style[b * IC + ic0 + i];
    }
    __syncthreads();
    int w = t >> 3, pp = t & 7;
    size_t base = (((size_t)b * HH + h) * WW + w) * IC + ic0;
    #pragma unroll
    for (int it = 0; it < 2; it++) {
        int ci = 2 * (it * 8 + pp);
        *(__half2*)(g_xm + base + ci) =
            __halves2half2(__float2half_rn(tile[ci][w]), __float2half_rn(tile[ci + 1][w]));
    }
}

// ---------------- main mma.sync conv kernel ----------------
// CTA tile: M=128 (4 h x 32 w) x N=128 oc. 8 warps (4 M x 2 N), warp 32x64.
// KC=64: A staged once per ic-chunk as 6x34 halo; B(tap) fp16, 3-stage
// cp.async pipeline (prefetch depth 2). 8 chunks x 9 taps x 4 k-slices.
#define KC 64
#define PAD_A 72   // halves per halo row (144 B: conflict-free ldmatrix)
#define PAD_B 72

// smem offsets in halves
#define A_O 0
#define B_O(buf) (14688 + (buf) * 9216)
#define SM_HALVES 42336      // 84672 bytes

__device__ __forceinline__ void mma_f16(float* c,
                                        const uint32_t* a, uint32_t b0, uint32_t b1) {
    asm volatile(
        "mma.sync.aligned.m16n8k16.row.col.f32.f16.f16.f32 "
        "{%0,%1,%2,%3}, {%4,%5,%6,%7}, {%8,%9}, {%0,%1,%2,%3};"
        : "+f"(c[0]), "+f"(c[1]), "+f"(c[2]), "+f"(c[3])
        : "r"(a[0]), "r"(a[1]), "r"(a[2]), "r"(a[3]), "r"(b0), "r"(b1));
}

__device__ __forceinline__ void ldsm4(uint32_t* r, uint32_t a) {
    asm volatile("ldmatrix.sync.aligned.m8n8.x4.shared.b16 {%0,%1,%2,%3}, [%4];"
                 : "=r"(r[0]), "=r"(r[1]), "=r"(r[2]), "=r"(r[3]) : "r"(a));
}

__device__ __forceinline__ void cp16(uint32_t dst, const void* src, bool v) {
    asm volatile("cp.async.ca.shared.global [%0], [%1], 16, %2;"
                 :: "r"(dst), "l"(src), "r"(v ? 16 : 0) : "memory");
}
#define CP_COMMIT() asm volatile("cp.async.commit_group;" ::: "memory")
#define CP_WAIT0()  asm volatile("cp.async.wait_group 0;" ::: "memory")
#define CP_WAIT1()  asm volatile("cp.async.wait_group 1;" ::: "memory")

__device__ __forceinline__ uint32_t smem_u32(const void* p) {
    uint32_t a;
    asm("{ .reg .u64 t; cvta.to.shared.u64 t, %1; cvt.u32.u64 %0, t; }" : "=r"(a) : "l"(p));
    return a;
}

__global__ __launch_bounds__(256, 2)
void conv_mma_kernel(float* __restrict__ y) {
    extern __shared__ unsigned short sm[];
    const uint32_t smb = smem_u32(sm);

    const int tid = threadIdx.x;
    const int wid = tid >> 5, lane = tid & 31;
    const int gr = lane >> 2, tig = lane & 3;
    const int wm = wid & 3;        // warp h-row
    const int wn = wid >> 2;       // warp oc half

    const int h0 = blockIdx.x * 4;
    const int oc0 = blockIdx.y * 128;
    const int b = blockIdx.z;

    // ---- ldmatrix lane address components ----
    const int r16 = ((lane >> 3) & 1) * 8 + (lane & 7);
    const int kq8 = (lane >> 4) * 8;
    int aoff0 = ((wm + 1) * 34 + r16 + 1) * PAD_A + kq8;
    const int rb = (lane & 7) + ((lane >> 4) & 1) * 8;
    const int kb8 = ((lane >> 3) & 1) * 8;
    const int boff = (wn * 64 + rb) * PAD_B + kb8;

    // ---- A halo loader coords (204 positions, 128B each) ----
    const int p = tid;
    const bool pa = p < 204;
    const int hi_ = p / 34, wi_ = p % 34;
    const int ha = h0 + hi_ - 1, wa = wi_ - 1;
    const bool va = pa && ((unsigned)ha < HH) && ((unsigned)wa < WW);
    const size_t aidx = (((size_t)b * HH + (va ? ha : 0)) * WW + (va ? wa : 0)) * IC;
    const uint32_t adst = smb + (uint32_t)(A_O + p * PAD_A) * 2;

    // ---- B loader coords: 2 threads per row, 64B each ----
    const int rB = tid >> 1, halfB = tid & 1;
    const size_t bRowBase = (size_t)(oc0 + rB) * IC + halfB * 32;
    const uint32_t bdst = (uint32_t)(rB * PAD_B + halfB * 32) * 2;

    float acc[2][8][4];
    #pragma unroll
    for (int mt = 0; mt < 2; mt++)
        #pragma unroll
        for (int nt = 0; nt < 8; nt++)
            #pragma unroll
            for (int q = 0; q < 4; q++) acc[mt][nt][q] = 0.f;

    for (int cc = 0; cc < 8; cc++) {
        const int ic0 = cc * KC;
        __syncthreads();   // protect A halo + B buffers from previous chunk's readers

        // group 0: A halo + B tap0 -> buf0
        if (pa) {
            #pragma unroll
            for (int j = 0; j < 8; j++)
                cp16(adst + j * 16, g_xm + aidx + ic0 + j * 8, va);
        }
        {
            const size_t src = bRowBase + ic0;
            uint32_t d_ = smb + (uint32_t)B_O(0) * 2 + bdst;
            #pragma unroll
            for (int j = 0; j < 4; j++)
                cp16(d_ + j * 16, g_wq + src + j * 8, true);
        }
        CP_COMMIT();
        // group 1: B tap1 -> buf1
        {
            const size_t src = (size_t)OC * IC + bRowBase + ic0;
            uint32_t d_ = smb + (uint32_t)B_O(1) * 2 + bdst;
            #pragma unroll
            for (int j = 0; j < 4; j++)
                cp16(d_ + j * 16, g_wq + src + j * 8, true);
        }
        CP_COMMIT();

        #pragma unroll
        for (int kk = 0; kk < 9; kk++) {
            if (kk < 7) { CP_WAIT1(); } else { CP_WAIT0(); }
            __syncthreads();
            if (kk < 7) {   // prefetch tap kk+2 -> buf (kk+2)%3
                const size_t src = (size_t)(kk + 2) * OC * IC + bRowBase + ic0;
                uint32_t d_ = smb + (uint32_t)B_O((kk + 2) % 3) * 2 + bdst;
                #pragma unroll
                for (int j = 0; j < 4; j++)
                    cp16(d_ + j * 16, g_wq + src + j * 8, true);
                CP_COMMIT();
            }

            // ---- compute tap kk from buf kk%3 ----
            const int dh = kk / 3 - 1, dw = kk % 3 - 1;
            const int tsh = (dh * 34 + dw) * PAD_A;
            const uint32_t bbase = smb + (uint32_t)(B_O(kk % 3) + boff) * 2;

            #pragma unroll
            for (int ks = 0; ks < 4; ks++) {
                uint32_t ah[2][4];
                #pragma unroll
                for (int mt = 0; mt < 2; mt++) {
                    uint32_t aa = smb + (uint32_t)(aoff0 + mt * 16 * PAD_A + tsh + ks * 16) * 2;
                    ldsm4(ah[mt], aa);
                }
                #pragma unroll
                for (int np = 0; np < 4; np++) {
                    uint32_t bh[4];
                    uint32_t ba = bbase + (uint32_t)(np * 16 * PAD_B + ks * 16) * 2;
                    ldsm4(bh, ba);
                    // same-accumulator distance = 4
                    mma_f16(acc[0][2 * np],     ah[0], bh[0], bh[1]);
                    mma_f16(acc[1][2 * np],     ah[1], bh[0], bh[1]);
                    mma_f16(acc[0][2 * np + 1], ah[0], bh[2], bh[3]);
                    mma_f16(acc[1][2 * np + 1], ah[1], bh[2], bh[3]);
                }
            }
        }
    }

    // ---- epilogue: demodulate + store ----
    const int h = h0 + wm;
    float scl[8][2];
    #pragma unroll
    for (int nt = 0; nt < 8; nt++) {
        int oc = oc0 + wn * 64 + nt * 8 + tig * 2;
        scl[nt][0] = g_scale[b * OC + oc];
        scl[nt][1] = g_scale[b * OC + oc + 1];
    }
    #pragma unroll
    for (int mt = 0; mt < 2; mt++) {
        int w0 = mt * 16 + gr;
        #pragma unroll
        for (int nt = 0; nt < 8; nt++) {
            int oc = oc0 + wn * 64 + nt * 8 + tig * 2;
            size_t base0 = (((size_t)b * OC + oc) * HH + h) * WW;
            size_t base1 = base0 + (size_t)HH * WW;
            y[base0 + w0]     = acc[mt][nt][0] * scl[nt][0];
            y[base1 + w0]     = acc[mt][nt][1] * scl[nt][1];
            y[base0 + w0 + 8] = acc[mt][nt][2] * scl[nt][0];
            y[base1 + w0 + 8] = acc[mt][nt][3] * scl[nt][1];
        }
    }
}

// ---------------------------------------------------------------------------
extern "C" void kernel_launch(void* const* d_in, const int* in_sizes, int n_in,
                              void* d_out, int out_size) {
    const float* x       = (const float*)d_in[0];
    const float* w       = (const float*)d_in[1];
    const float* conv_w  = (const float*)d_in[2];
    const float* dense_w = (const float*)d_in[3];
    const float* dense_b = (const float*)d_in[4];
    float* y = (float*)d_out;

    style_kernel<<<BN, 256>>>(w, dense_w, dense_b);
    wtrans_kernel<<<dim3(IC / 32, OC / 32), 256>>>(conv_w);   // + fused ss
    demod_kernel<<<BN, 512>>>();
    xtrans_kernel<<<dim3(IC / 32, HH, BN), 256>>>(x);

    static bool attr_set = false;
    if (!attr_set) {
        cudaFuncSetAttribute(conv_mma_kernel,
                             cudaFuncAttributeMaxDynamicSharedMemorySize, SM_HALVES * 2);
        attr_set = true;
    }
    conv_mma_kernel<<<dim3(8, 4, BN), 256, SM_HALVES * 2>>>(y);
}